// round 10
// baseline (speedup 1.0000x reference)
#include <cuda_runtime.h>
#include <math.h>

// Problem constants
#define NFFT     1024
#define HOP      256
#define SIGLEN   524288
#define NBATCH   32
#define GROUP    8            // output frames per CTA
#define NFRAMES  9            // FFT frames per CTA (GROUP+1)
#define NBINS    512          // output freq bins (k = 1..512)
#define THREADS  512
#define XBUFLEN  (GROUP*HOP + NFFT)   // 3072

// precomputed tables (filled by init kernel, double-precision accurate)
__device__ float2 g_tw[NFFT];    // exp(-2*pi*i*t/1024)
__device__ float  g_win[NFFT];   // periodic hann

__global__ void init_tables()
{
    int t = blockIdx.x * blockDim.x + threadIdx.x;
    if (t < NFFT) {
        double ang = -2.0 * 3.14159265358979323846 * (double)t / 1024.0;
        double s, c;
        sincos(ang, &s, &c);
        g_tw[t] = make_float2((float)c, (float)s);
        g_win[t] = (float)(0.5 * (1.0 - cos(2.0 * 3.14159265358979323846 * (double)t / 1024.0)));
    }
}

__device__ __forceinline__ float wrap_pi(float d) {
    const float INV2PI = 0.15915494309189535f;
    const float TWOPI  = 6.283185307179586f;
    return d - TWOPI * rintf(d * INV2PI);
}

__device__ __forceinline__ float2 cmul(float2 a, float2 b) {
    return make_float2(a.x * b.x - a.y * b.y, a.x * b.y + a.y * b.x);
}

__device__ __forceinline__ float2 shflx(float2 v, int m) {
    float px = __shfl_xor_sync(0xffffffffu, v.x, m);
    float py = __shfl_xor_sync(0xffffffffu, v.y, m);
    return make_float2(px, py);
}

// 32-point DIF FFT across the 32 lanes of a warp.
// Input: lane l holds x[l]. Output: lane l holds X[brev5(l)].
__device__ __forceinline__ float2 wfft32(float2 v, int lane,
                                         float2 t16, float2 t8, float2 t4)
{
    float2 p;
    p = shflx(v, 16);
    if (lane & 16) v = cmul(make_float2(p.x - v.x, p.y - v.y), t16);
    else           v = make_float2(v.x + p.x, v.y + p.y);

    p = shflx(v, 8);
    if (lane & 8)  v = cmul(make_float2(p.x - v.x, p.y - v.y), t8);
    else           v = make_float2(v.x + p.x, v.y + p.y);

    p = shflx(v, 4);
    if (lane & 4)  v = cmul(make_float2(p.x - v.x, p.y - v.y), t4);
    else           v = make_float2(v.x + p.x, v.y + p.y);

    p = shflx(v, 2);
    if (lane & 2) {
        float2 s = make_float2(p.x - v.x, p.y - v.y);
        v = (lane & 1) ? make_float2(s.y, -s.x) : s;  // *(-i) when j==1
    } else {
        v = make_float2(v.x + p.x, v.y + p.y);
    }

    p = shflx(v, 1);
    if (lane & 1)  v = make_float2(p.x - v.x, p.y - v.y);
    else           v = make_float2(v.x + p.x, v.y + p.y);
    return v;
}

// padded index: +1 per 32 (conflict-free for stride-32 access)
__device__ __forceinline__ int P(int i) { return i + (i >> 5); }

extern __shared__ float smem_raw[];

__global__ __launch_bounds__(THREADS, 3)
void stft_kernel(const float* __restrict__ x, float* __restrict__ out)
{
    // ---- shared layout ----
    float*  winP  = smem_raw;                    // 1056 floats
    float*  xbufP = winP + 1056;                 // 3168 floats
    float2* Ys    = (float2*)(xbufP + 3168);     // 1056 float2 (kk*33 + b)
    float2* Sf    = Ys + 1056;                   // 1056 float2 (P(k))
    float*  lm    = (float*)(Sf + 1056);         // 8*512 floats
    float*  dd    = lm + GROUP * NBINS;          // 8*512 floats
    // total = (1056+3168)*4 + 1056*8*2 + 4096*4*2 = 66560 B

    const int tid  = threadIdx.x;
    const int w    = tid >> 5;
    const int lane = tid & 31;
    const int grp  = blockIdx.x;   // 0..255
    const int b    = blockIdx.y;   // 0..31

    // ---- stage window into smem (coalesced) ----
    #pragma unroll
    for (int i = tid; i < NFFT; i += THREADS)
        winP[P(i)] = g_win[i];

    // ---- per-thread loop-invariant constants ----
    const float2 t16 = g_tw[(lane & 15) << 5];
    const float2 t8  = g_tw[(lane & 7)  << 6];
    const float2 t4  = g_tw[(lane & 3)  << 7];
    const int    kk  = (int)(__brev((unsigned)lane) >> 27);  // brev5(lane)

    const int b0 = 2 * w;
    const int b1 = 2 * w + 1;
    const int n0 = (lane << 5) + b0;
    const int n1 = (lane << 5) + b1;

    // step-2 twiddles W1024^(b*k1), invariant across the 5 FFTs
    const float2 twA = g_tw[b0 * kk];
    const float2 twB = g_tw[b1 * kk];

    // ---- load input window with reflect padding ----
    {
        const long base = (long)grp * (GROUP * HOP) - (NFFT / 2);
        const float* xb = x + (long)b * SIGLEN;
        #pragma unroll
        for (int i = tid; i < XBUFLEN; i += THREADS) {
            long p = base + i;
            if (p < 0) p = -p;
            else if (p >= SIGLEN) p = 2L * (SIGLEN - 1) - p;
            xbufP[P(i)] = xb[p];
        }
    }
    __syncthreads();

    const float w0v = winP[P(n0)];
    const float w1v = winP[P(n1)];

    float prevPh = 0.0f;

    // ---- 5 complex FFTs covering 9 real frames (pairs packed in re/im) ----
    #pragma unroll
    for (int pr = 0; pr < 5; pr++) {
        const int gA = 2 * pr;
        const int gB = 2 * pr + 1;
        const bool hasB = (gB < NFRAMES);

        // ===== step 1: 32-pt FFT over lane dim for columns b0, b1 =====
        {
            float2 v0, v1;
            v0.x = w0v * xbufP[P(gA * HOP + n0)];
            v1.x = w1v * xbufP[P(gA * HOP + n1)];
            if (hasB) {
                v0.y = w0v * xbufP[P(gB * HOP + n0)];
                v1.y = w1v * xbufP[P(gB * HOP + n1)];
            } else {
                v0.y = 0.0f; v1.y = 0.0f;
            }

            v0 = wfft32(v0, lane, t16, t8, t4);   // Y[k1=kk, b0]
            v1 = wfft32(v1, lane, t16, t8, t4);   // Y[k1=kk, b1]

            // ===== step 2: twiddle =====
            v0 = cmul(v0, twA);
            v1 = cmul(v1, twB);

            // transpose store
            Ys[kk * 33 + b0] = v0;
            Ys[kk * 33 + b1] = v1;
        }
        __syncthreads();   // Ys write -> Ys read

        // ===== step 3: 32-pt FFT over b for rows k1 = b0, b1 =====
        {
            float2 u0 = Ys[b0 * 33 + lane];
            float2 u1 = Ys[b1 * 33 + lane];
            u0 = wfft32(u0, lane, t16, t8, t4);   // X[b0 + 32*kk]
            u1 = wfft32(u1, lane, t16, t8, t4);   // X[b1 + 32*kk]
            Sf[P(b0 + (kk << 5))] = u0;
            Sf[P(b1 + (kk << 5))] = u1;
        }
        __syncthreads();   // S write -> S read (also orders Ys reuse)

        // ===== unpack packed real spectra; k = tid+1 (skip DC) =====
        {
            const int k = tid + 1;
            const int r = NFFT - k;
            const float2 zk = Sf[P(k)];
            const float2 zr = Sf[P(r)];
            // A = spectrum of frame gA
            const float Are = 0.5f * (zk.x + zr.x);
            const float Aim = 0.5f * (zk.y - zr.y);
            const float phA = atan2f(Aim, Are);
            if (pr > 0) {
                dd[(gA - 1) * NBINS + tid] = wrap_pi(phA - prevPh);
                const float m2 = Are * Are + Aim * Aim;
                lm[(gA - 1) * NBINS + tid] =
                    (0.5f * __logf(fmaxf(m2, 1e-14f)) + 17.0f) * (1.0f / 23.0f);
            }
            if (hasB) {
                // B = spectrum of frame gB
                const float Bre = 0.5f * (zk.y + zr.y);
                const float Bim = 0.5f * (zr.x - zk.x);
                const float phB = atan2f(Bim, Bre);
                dd[(gB - 1) * NBINS + tid] = wrap_pi(phB - phA);
                const float m2 = Bre * Bre + Bim * Bim;
                lm[(gB - 1) * NBINS + tid] =
                    (0.5f * __logf(fmaxf(m2, 1e-14f)) + 17.0f) * (1.0f / 23.0f);
                prevPh = phB;
            }
        }
        // no sync needed here: next iter's first sync orders S/Ys reuse
    }

    // ---- writeout: thread tid owns freq row f = tid ----
    // lm/dd columns were written by this same thread -> no sync needed.
    {
        const long t0 = (long)grp * GROUP;
        float* o0 = out + ((((long)b * 2 + 0) * 512 + tid) * 2048 + t0);
        float* o1 = out + ((((long)b * 2 + 1) * 512 + tid) * 2048 + t0);
        ((float4*)o0)[0] = make_float4(lm[0 * NBINS + tid], lm[1 * NBINS + tid],
                                       lm[2 * NBINS + tid], lm[3 * NBINS + tid]);
        ((float4*)o0)[1] = make_float4(lm[4 * NBINS + tid], lm[5 * NBINS + tid],
                                       lm[6 * NBINS + tid], lm[7 * NBINS + tid]);
        ((float4*)o1)[0] = make_float4(dd[0 * NBINS + tid], dd[1 * NBINS + tid],
                                       dd[2 * NBINS + tid], dd[3 * NBINS + tid]);
        ((float4*)o1)[1] = make_float4(dd[4 * NBINS + tid], dd[5 * NBINS + tid],
                                       dd[6 * NBINS + tid], dd[7 * NBINS + tid]);
    }
}

extern "C" void kernel_launch(void* const* d_in, const int* in_sizes, int n_in,
                              void* d_out, int out_size)
{
    (void)in_sizes; (void)n_in; (void)out_size;
    const float* x = (const float*)d_in[0];
    float* out = (float*)d_out;

    init_tables<<<2, 512>>>();

    const size_t shmem = 66560;   // bytes
    cudaFuncSetAttribute(stft_kernel,
                         cudaFuncAttributeMaxDynamicSharedMemorySize,
                         (int)shmem);

    dim3 grid(2048 / GROUP, NBATCH);   // (256, 32)
    stft_kernel<<<grid, THREADS, shmem>>>(x, out);
}

// round 11
// speedup vs baseline: 1.0584x; 1.0584x over previous
#include <cuda_runtime.h>
#include <math.h>

// Problem constants
#define NFFT     1024
#define HOP      256
#define SIGLEN   524288
#define NBATCH   32
#define GROUP    8            // output frames per CTA
#define NFRAMES  9            // FFT frames per CTA (GROUP+1)
#define NBINS    512          // output freq bins (k = 1..512)
#define THREADS  512
#define XBUFLEN  (GROUP*HOP + NFFT)   // 3072

// precomputed tables (filled by init kernel, double-precision accurate)
__device__ float2 g_tw[NFFT];    // exp(-2*pi*i*t/1024)
__device__ float  g_win[NFFT];   // periodic hann

__global__ void init_tables()
{
    int t = blockIdx.x * blockDim.x + threadIdx.x;
    if (t < NFFT) {
        double ang = -2.0 * 3.14159265358979323846 * (double)t / 1024.0;
        double s, c;
        sincos(ang, &s, &c);
        g_tw[t] = make_float2((float)c, (float)s);
        g_win[t] = (float)(0.5 * (1.0 - cos(2.0 * 3.14159265358979323846 * (double)t / 1024.0)));
    }
}

__device__ __forceinline__ float wrap_pi(float d) {
    const float INV2PI = 0.15915494309189535f;
    const float TWOPI  = 6.283185307179586f;
    return d - TWOPI * rintf(d * INV2PI);
}

__device__ __forceinline__ float2 cmul(float2 a, float2 b) {
    return make_float2(a.x * b.x - a.y * b.y, a.x * b.y + a.y * b.x);
}

__device__ __forceinline__ float2 shflx(float2 v, int m) {
    float px = __shfl_xor_sync(0xffffffffu, v.x, m);
    float py = __shfl_xor_sync(0xffffffffu, v.y, m);
    return make_float2(px, py);
}

// 32-point DIF FFT across the 32 lanes of a warp.
// Input: lane l holds x[l]. Output: lane l holds X[brev5(l)].
__device__ __forceinline__ float2 wfft32(float2 v, int lane,
                                         float2 t16, float2 t8, float2 t4)
{
    float2 p;
    p = shflx(v, 16);
    if (lane & 16) v = cmul(make_float2(p.x - v.x, p.y - v.y), t16);
    else           v = make_float2(v.x + p.x, v.y + p.y);

    p = shflx(v, 8);
    if (lane & 8)  v = cmul(make_float2(p.x - v.x, p.y - v.y), t8);
    else           v = make_float2(v.x + p.x, v.y + p.y);

    p = shflx(v, 4);
    if (lane & 4)  v = cmul(make_float2(p.x - v.x, p.y - v.y), t4);
    else           v = make_float2(v.x + p.x, v.y + p.y);

    p = shflx(v, 2);
    if (lane & 2) {
        float2 s = make_float2(p.x - v.x, p.y - v.y);
        v = (lane & 1) ? make_float2(s.y, -s.x) : s;  // *(-i) when j==1
    } else {
        v = make_float2(v.x + p.x, v.y + p.y);
    }

    p = shflx(v, 1);
    if (lane & 1)  v = make_float2(p.x - v.x, p.y - v.y);
    else           v = make_float2(v.x + p.x, v.y + p.y);
    return v;
}

// padded index: +1 per 32 (conflict-free for stride-32 access)
__device__ __forceinline__ int P(int i) { return i + (i >> 5); }

extern __shared__ float smem_raw[];

__global__ __launch_bounds__(THREADS, 3)
void stft_kernel(const float* __restrict__ x, float* __restrict__ out)
{
    // ---- shared layout ----
    float*  winP  = smem_raw;                    // 1056 floats
    float*  xbufP = winP + 1056;                 // 3168 floats
    float2* Ys    = (float2*)(xbufP + 3168);     // 1056 float2 (kk*33 + b)
    float2* Sf    = Ys + 1056;                   // 1056 float2 (P(k))
    float*  lm    = (float*)(Sf + 1056);         // 8*512 floats
    float*  dd    = lm + GROUP * NBINS;          // 8*512 floats
    // total = (1056+3168)*4 + 1056*8*2 + 4096*4*2 = 66560 B

    const int tid  = threadIdx.x;
    const int w    = tid >> 5;
    const int lane = tid & 31;
    const int grp  = blockIdx.x;   // 0..255
    const int b    = blockIdx.y;   // 0..31

    // ---- stage window into smem (coalesced) ----
    #pragma unroll
    for (int i = tid; i < NFFT; i += THREADS)
        winP[P(i)] = g_win[i];

    // ---- per-thread loop-invariant constants ----
    const float2 t16 = g_tw[(lane & 15) << 5];
    const float2 t8  = g_tw[(lane & 7)  << 6];
    const float2 t4  = g_tw[(lane & 3)  << 7];
    const int    kk  = (int)(__brev((unsigned)lane) >> 27);  // brev5(lane)

    const int b0 = 2 * w;
    const int b1 = 2 * w + 1;
    const int n0 = (lane << 5) + b0;
    const int n1 = (lane << 5) + b1;

    // step-2 twiddles W1024^(b*k1), invariant across the 5 FFTs
    const float2 twA = g_tw[b0 * kk];
    const float2 twB = g_tw[b1 * kk];

    // ---- load input window with reflect padding ----
    {
        const long base = (long)grp * (GROUP * HOP) - (NFFT / 2);
        const float* xb = x + (long)b * SIGLEN;
        #pragma unroll
        for (int i = tid; i < XBUFLEN; i += THREADS) {
            long p = base + i;
            if (p < 0) p = -p;
            else if (p >= SIGLEN) p = 2L * (SIGLEN - 1) - p;
            xbufP[P(i)] = xb[p];
        }
    }
    __syncthreads();

    const float w0v = winP[P(n0)];
    const float w1v = winP[P(n1)];

    float prevPh = 0.0f;

    // ---- 5 complex FFTs covering 9 real frames (pairs packed in re/im) ----
    #pragma unroll
    for (int pr = 0; pr < 5; pr++) {
        const int gA = 2 * pr;
        const int gB = 2 * pr + 1;
        const bool hasB = (gB < NFRAMES);

        // ===== step 1: 32-pt FFT over lane dim for columns b0, b1 =====
        {
            float2 v0, v1;
            v0.x = w0v * xbufP[P(gA * HOP + n0)];
            v1.x = w1v * xbufP[P(gA * HOP + n1)];
            if (hasB) {
                v0.y = w0v * xbufP[P(gB * HOP + n0)];
                v1.y = w1v * xbufP[P(gB * HOP + n1)];
            } else {
                v0.y = 0.0f; v1.y = 0.0f;
            }

            v0 = wfft32(v0, lane, t16, t8, t4);   // Y[k1=kk, b0]
            v1 = wfft32(v1, lane, t16, t8, t4);   // Y[k1=kk, b1]

            // ===== step 2: twiddle =====
            v0 = cmul(v0, twA);
            v1 = cmul(v1, twB);

            // transpose store
            Ys[kk * 33 + b0] = v0;
            Ys[kk * 33 + b1] = v1;
        }
        __syncthreads();   // Ys write -> Ys read

        // ===== step 3: 32-pt FFT over b for rows k1 = b0, b1 =====
        {
            float2 u0 = Ys[b0 * 33 + lane];
            float2 u1 = Ys[b1 * 33 + lane];
            u0 = wfft32(u0, lane, t16, t8, t4);   // X[b0 + 32*kk]
            u1 = wfft32(u1, lane, t16, t8, t4);   // X[b1 + 32*kk]
            Sf[P(b0 + (kk << 5))] = u0;
            Sf[P(b1 + (kk << 5))] = u1;
        }
        __syncthreads();   // S write -> S read (also orders Ys reuse)

        // ===== unpack packed real spectra; k = tid+1 (skip DC) =====
        {
            const int k = tid + 1;
            const int r = NFFT - k;
            const float2 zk = Sf[P(k)];
            const float2 zr = Sf[P(r)];
            // A = spectrum of frame gA
            const float Are = 0.5f * (zk.x + zr.x);
            const float Aim = 0.5f * (zk.y - zr.y);
            const float phA = atan2f(Aim, Are);
            if (pr > 0) {
                dd[(gA - 1) * NBINS + tid] = wrap_pi(phA - prevPh);
                const float m2 = Are * Are + Aim * Aim;
                lm[(gA - 1) * NBINS + tid] =
                    (0.5f * __logf(fmaxf(m2, 1e-14f)) + 17.0f) * (1.0f / 23.0f);
            }
            if (hasB) {
                // B = spectrum of frame gB
                const float Bre = 0.5f * (zk.y + zr.y);
                const float Bim = 0.5f * (zr.x - zk.x);
                const float phB = atan2f(Bim, Bre);
                dd[(gB - 1) * NBINS + tid] = wrap_pi(phB - phA);
                const float m2 = Bre * Bre + Bim * Bim;
                lm[(gB - 1) * NBINS + tid] =
                    (0.5f * __logf(fmaxf(m2, 1e-14f)) + 17.0f) * (1.0f / 23.0f);
                prevPh = phB;
            }
        }
        // no sync needed here: next iter's first sync orders S/Ys reuse
    }

    // ---- writeout: thread tid owns freq row f = tid ----
    // lm/dd columns were written by this same thread -> no sync needed.
    {
        const long t0 = (long)grp * GROUP;
        float* o0 = out + ((((long)b * 2 + 0) * 512 + tid) * 2048 + t0);
        float* o1 = out + ((((long)b * 2 + 1) * 512 + tid) * 2048 + t0);
        ((float4*)o0)[0] = make_float4(lm[0 * NBINS + tid], lm[1 * NBINS + tid],
                                       lm[2 * NBINS + tid], lm[3 * NBINS + tid]);
        ((float4*)o0)[1] = make_float4(lm[4 * NBINS + tid], lm[5 * NBINS + tid],
                                       lm[6 * NBINS + tid], lm[7 * NBINS + tid]);
        ((float4*)o1)[0] = make_float4(dd[0 * NBINS + tid], dd[1 * NBINS + tid],
                                       dd[2 * NBINS + tid], dd[3 * NBINS + tid]);
        ((float4*)o1)[1] = make_float4(dd[4 * NBINS + tid], dd[5 * NBINS + tid],
                                       dd[6 * NBINS + tid], dd[7 * NBINS + tid]);
    }
}

extern "C" void kernel_launch(void* const* d_in, const int* in_sizes, int n_in,
                              void* d_out, int out_size)
{
    (void)in_sizes; (void)n_in; (void)out_size;
    const float* x = (const float*)d_in[0];
    float* out = (float*)d_out;

    init_tables<<<2, 512>>>();

    const size_t shmem = 66560;   // bytes
    cudaFuncSetAttribute(stft_kernel,
                         cudaFuncAttributeMaxDynamicSharedMemorySize,
                         (int)shmem);

    dim3 grid(2048 / GROUP, NBATCH);   // (256, 32)
    stft_kernel<<<grid, THREADS, shmem>>>(x, out);
}